// round 3
// baseline (speedup 1.0000x reference)
#include <cuda_runtime.h>

#define NB 16
#define NN 4096
#define NE 131072
#define NH 16
#define NT 3
#define NFC 20
#define BHD 256                     // B*H = 256 floats per node row
#define INV_SQRT_DEG 0.17677669529663687f   // 1/sqrt(E/N) = 1/sqrt(32)

// ---------------- device scratch (static: no allocs allowed) ----------------
__device__ __align__(16) float g_h0[NN * BHD];     // 4 MB ping
__device__ __align__(16) float g_h1[NN * BHD];     // 4 MB pong
__device__ __align__(16) float g_A[NN * 48];       // a[i][b*3+p]
__device__ __align__(16) float g_C[NN * 48];       // c[j][b*3+q]
__device__ __align__(16) float g_R[4 * NN * 48];   // partial R = W2 @ C (4 K-splits)
__device__ int   g_cnt[NN];
__device__ int   g_rowptr[NN + 1];
__device__ int   g_cursor[NN];
__device__ int   g_csr[NE];                        // src | (type<<16), sorted by dst
__device__ float g_ew[2 * NT];                     // per-layer per-type edge weight
__device__ float g_invF[NB * 9];

// ---------------- init: zero counters, edge weights, inv(F) ----------------
__global__ void k_init(const float* __restrict__ F,
                       const float* __restrict__ fc10, const float* __restrict__ fc20,
                       const float* __restrict__ fc11, const float* __restrict__ fc21) {
    int tid = threadIdx.x;
    for (int i = tid; i < NN; i += 256) g_cnt[i] = 0;
    if (tid < 6) {
        int l = tid / 3, t = tid % 3;
        const float* f1 = l ? fc11 : fc10;
        const float* f2 = l ? fc21 : fc20;
        float s = 0.f;
        #pragma unroll
        for (int f = 0; f < NFC; f++) s = fmaf(fmaxf(f1[t * NFC + f], 0.f), f2[f], s);
        g_ew[tid] = s;
    }
    if (tid >= 32 && tid < 32 + NB) {
        int b = tid - 32;
        const float* m = F + b * 9;
        float a00=m[0],a01=m[1],a02=m[2],a10=m[3],a11=m[4],a12=m[5],a20=m[6],a21=m[7],a22=m[8];
        float det = a00*(a11*a22-a12*a21) - a01*(a10*a22-a12*a20) + a02*(a10*a21-a11*a20);
        float id = 1.f / det;
        float* o = g_invF + b * 9;
        o[0]=(a11*a22-a12*a21)*id; o[1]=(a02*a21-a01*a22)*id; o[2]=(a01*a12-a02*a11)*id;
        o[3]=(a12*a20-a10*a22)*id; o[4]=(a00*a22-a02*a20)*id; o[5]=(a02*a10-a00*a12)*id;
        o[6]=(a10*a21-a11*a20)*id; o[7]=(a01*a20-a00*a21)*id; o[8]=(a00*a11-a01*a10)*id;
    }
}

// ---------------- CSR build ----------------
__global__ void k_hist(const int* __restrict__ edge_dst) {
    int e = blockIdx.x * 256 + threadIdx.x;
    if (e < NE) atomicAdd(&g_cnt[edge_dst[e]], 1);
}

__global__ void k_scan() {   // 1 block, 1024 threads, 4 items/thread
    int tid = threadIdx.x;
    int v[4]; int s = 0;
    #pragma unroll
    for (int j = 0; j < 4; j++) { v[j] = g_cnt[tid * 4 + j]; s += v[j]; }
    int lane = tid & 31, wid = tid >> 5;
    const unsigned full = 0xFFFFFFFFu;
    int x = s;
    #pragma unroll
    for (int off = 1; off < 32; off <<= 1) { int y = __shfl_up_sync(full, x, off); if (lane >= off) x += y; }
    __shared__ int swarp[32];
    if (lane == 31) swarp[wid] = x;
    __syncthreads();
    if (wid == 0) {
        int y = swarp[lane];
        #pragma unroll
        for (int off = 1; off < 32; off <<= 1) { int z = __shfl_up_sync(full, y, off); if (lane >= off) y += z; }
        swarp[lane] = y;
    }
    __syncthreads();
    int base = (x - s) + (wid > 0 ? swarp[wid - 1] : 0);
    int run = base;
    #pragma unroll
    for (int j = 0; j < 4; j++) {
        g_rowptr[tid * 4 + j] = run;
        g_cursor[tid * 4 + j] = run;
        run += v[j];
    }
    if (tid == 1023) g_rowptr[NN] = run;
}

__global__ void k_scatter(const int* __restrict__ edge_src,
                          const int* __restrict__ edge_dst,
                          const int* __restrict__ edge_type) {
    int e = blockIdx.x * 256 + threadIdx.x;
    if (e < NE) {
        int pos = atomicAdd(&g_cursor[edge_dst[e]], 1);
        g_csr[pos] = edge_src[e] | (edge_type[e] << 16);
    }
}

// ---------------- h0 = (F @ pos) @ W_in ----------------
__global__ void k_h0(const float* __restrict__ F, const float* __restrict__ node_pos,
                     const float* __restrict__ W_in) {
    int n = blockIdx.x, tid = threadIdx.x;
    int b = tid >> 4, k = tid & 15;
    __shared__ float sp[3];
    if (tid < 3) sp[tid] = node_pos[n * 3 + tid];
    __syncthreads();
    float h = 0.f;
    #pragma unroll
    for (int i = 0; i < 3; i++) {
        float fx = F[b*9 + i*3 + 0]*sp[0] + F[b*9 + i*3 + 1]*sp[1] + F[b*9 + i*3 + 2]*sp[2];
        h = fmaf(fx, W_in[i * 16 + k], h);
    }
    g_h0[n * BHD + tid] = h;
}

// ---------------- one GNN layer: gather-by-dst, scale, @Wl, relu ----------------
// NOTE: hin/hout resolved from device symbols INSIDE the kernel. Passing
// __device__ globals as host-side kernel args passes the host shadow address
// (garbage on device) — that was the R2 correctness bug.
__global__ void k_layer(const float* __restrict__ Wl, int layer) {
    const float* __restrict__ hin  = layer ? g_h1 : g_h0;
    float*       __restrict__ hout = layer ? g_h0 : g_h1;
    int n = blockIdx.x, tid = threadIdx.x;
    __shared__ float sW[256], sagg[256], sew[3];
    __shared__ int sedge[128];
    sW[tid] = Wl[tid];
    if (tid < 3) sew[tid] = g_ew[layer * 3 + tid];
    int start = g_rowptr[n], end = g_rowptr[n + 1];
    float acc = 0.f;
    for (int base = start; base < end; base += 128) {
        int cnt = min(128, end - base);
        __syncthreads();
        if (tid < cnt) sedge[tid] = g_csr[base + tid];
        __syncthreads();
        int i = 0;
        for (; i + 4 <= cnt; i += 4) {
            int p0 = sedge[i], p1 = sedge[i+1], p2 = sedge[i+2], p3 = sedge[i+3];
            float v0 = hin[(p0 & 0xFFFF) * BHD + tid];
            float v1 = hin[(p1 & 0xFFFF) * BHD + tid];
            float v2 = hin[(p2 & 0xFFFF) * BHD + tid];
            float v3 = hin[(p3 & 0xFFFF) * BHD + tid];
            acc = fmaf(sew[p0 >> 16], v0, acc);
            acc = fmaf(sew[p1 >> 16], v1, acc);
            acc = fmaf(sew[p2 >> 16], v2, acc);
            acc = fmaf(sew[p3 >> 16], v3, acc);
        }
        for (; i < cnt; i++) {
            int p = sedge[i];
            acc = fmaf(sew[p >> 16], hin[(p & 0xFFFF) * BHD + tid], acc);
        }
    }
    __syncthreads();
    sagg[tid] = acc * INV_SQRT_DEG;
    __syncthreads();
    int b = tid >> 4, k = tid & 15;
    const float* ar = &sagg[b * 16];
    float s = 0.f;
    #pragma unroll
    for (int kk = 0; kk < 16; kk++) s = fmaf(ar[kk], sW[kk * 16 + k], s);
    hout[n * BHD + tid] = fmaxf(s, 0.f);
}

// ---------------- head: a & c for the first N edges ----------------
__global__ void k_head(const int* __restrict__ edge_src, const int* __restrict__ edge_dst,
                       const float* __restrict__ W_out) {
    int e = blockIdx.x, tid = threadIdx.x;
    __shared__ float sd[256], sa[48];
    int src = edge_src[e], dst = edge_dst[e];
    sd[tid] = g_h0[src * BHD + tid] - g_h0[dst * BHD + tid];
    __syncthreads();
    if (tid < 48) {
        int b = tid / 3, p = tid % 3;
        float a = 0.f;
        #pragma unroll
        for (int k = 0; k < 16; k++) a = fmaf(sd[b * 16 + k], W_out[k * 3 + p], a);
        sa[tid] = a;
        g_A[e * 48 + tid] = a;
    }
    __syncthreads();
    if (tid < 48) {
        int b = tid / 3, q = tid % 3;
        float c = 0.f;
        #pragma unroll
        for (int p = 0; p < 3; p++) c = fmaf(g_invF[b * 9 + q * 3 + p], sa[b * 3 + p], c);
        g_C[e * 48 + tid] = c;
    }
}

// ---------------- R = W2 @ C, 128-row blocks, 4-way K split ----------------
__global__ void __launch_bounds__(256) k_gemm(const float* __restrict__ W2) {
    int i0 = blockIdx.x * 128;
    int js = blockIdx.y;
    int j0base = js * 1024;
    __shared__ float Ws[128 * 65];
    __shared__ __align__(16) float Cs[64 * 48];
    int tid = threadIdx.x;
    int tr = tid & 31, tc = tid >> 5;        // tr: row group, tc: 6-col group
    float acc[4][6];
    #pragma unroll
    for (int m = 0; m < 4; m++)
        #pragma unroll
        for (int u = 0; u < 6; u++) acc[m][u] = 0.f;

    for (int jc = 0; jc < 16; jc++) {
        int j0 = j0base + jc * 64;
        __syncthreads();
        // load C chunk [64 x 48] (fully contiguous in gmem)
        const float4* cg = (const float4*)(g_C + j0 * 48);
        float4* cs = (float4*)Cs;
        for (int t = tid; t < 768; t += 256) cs[t] = cg[t];
        // load W2 tile [128 x 64] coalesced, pitch-65 smem (conflict-free)
        #pragma unroll
        for (int rep = 0; rep < 8; rep++) {
            int f = rep * 256 + tid;
            int r = f >> 4, c4 = f & 15;
            float4 w = *(const float4*)(W2 + (size_t)(i0 + r) * NN + j0 + c4 * 4);
            float* wd = &Ws[r * 65 + c4 * 4];
            wd[0] = w.x; wd[1] = w.y; wd[2] = w.z; wd[3] = w.w;
        }
        __syncthreads();
        #pragma unroll 8
        for (int jj = 0; jj < 64; jj++) {
            float wv[4];
            #pragma unroll
            for (int m = 0; m < 4; m++) wv[m] = Ws[(tr + 32 * m) * 65 + jj];
            const float* cp = &Cs[jj * 48 + tc * 6];
            #pragma unroll
            for (int u = 0; u < 6; u++) {
                float cv = cp[u];
                #pragma unroll
                for (int m = 0; m < 4; m++) acc[m][u] = fmaf(wv[m], cv, acc[m][u]);
            }
        }
    }
    float* out = g_R + (size_t)js * NN * 48;
    #pragma unroll
    for (int m = 0; m < 4; m++) {
        int i = i0 + tr + 32 * m;
        #pragma unroll
        for (int u = 0; u < 6; u++) out[i * 48 + tc * 6 + u] = acc[m][u];
    }
}

// ---------------- stress[b,p,q] = sum_i A[i][b,p] * R[i][b,q] ----------------
__global__ void k_final(float* __restrict__ out) {
    int idx = blockIdx.x;              // 0..143
    int b = idx / 9, r = idx % 9, p = r / 3, q = r % 3;
    int cp = b * 3 + p, cq = b * 3 + q;
    int tid = threadIdx.x;
    float s = 0.f;
    for (int i = tid; i < NN; i += 256) {
        float rv = g_R[i * 48 + cq] + g_R[NN * 48 + i * 48 + cq]
                 + g_R[2 * NN * 48 + i * 48 + cq] + g_R[3 * NN * 48 + i * 48 + cq];
        s = fmaf(g_A[i * 48 + cp], rv, s);
    }
    // block reduce
    const unsigned full = 0xFFFFFFFFu;
    #pragma unroll
    for (int off = 16; off > 0; off >>= 1) s += __shfl_down_sync(full, s, off);
    __shared__ float red[8];
    int lane = tid & 31, wid = tid >> 5;
    if (lane == 0) red[wid] = s;
    __syncthreads();
    if (tid == 0) {
        float t = 0.f;
        #pragma unroll
        for (int w = 0; w < 8; w++) t += red[w];
        out[idx] = t;
    }
}

// ---------------- launch ----------------
extern "C" void kernel_launch(void* const* d_in, const int* in_sizes, int n_in,
                              void* d_out, int out_size) {
    const float* F        = (const float*)d_in[0];
    const float* node_pos = (const float*)d_in[1];
    const int*   edge_src = (const int*)d_in[2];
    const int*   edge_dst = (const int*)d_in[3];
    const int*   edge_type= (const int*)d_in[4];
    const float* W_in     = (const float*)d_in[5];
    const float* fc1_0    = (const float*)d_in[6];
    const float* fc2_0    = (const float*)d_in[7];
    const float* W_0      = (const float*)d_in[8];
    const float* fc1_1    = (const float*)d_in[9];
    const float* fc2_1    = (const float*)d_in[10];
    const float* W_1      = (const float*)d_in[11];
    const float* W_out    = (const float*)d_in[12];
    const float* w        = (const float*)d_in[13];
    float* out = (float*)d_out;

    k_init<<<1, 256>>>(F, fc1_0, fc2_0, fc1_1, fc2_1);
    k_hist<<<NE / 256, 256>>>(edge_dst);
    k_scan<<<1, 1024>>>();
    k_scatter<<<NE / 256, 256>>>(edge_src, edge_dst, edge_type);
    k_h0<<<NN, 256>>>(F, node_pos, W_in);
    k_layer<<<NN, 256>>>(W_0, 0);
    k_layer<<<NN, 256>>>(W_1, 1);
    k_head<<<NN, 256>>>(edge_src, edge_dst, W_out);
    k_gemm<<<dim3(32, 4), 256>>>(w);
    k_final<<<144, 256>>>(out);
}